// round 4
// baseline (speedup 1.0000x reference)
#include <cuda_runtime.h>
#include <cuda_bf16.h>
#include <cuda_fp8.h>
#include <cstdint>

// Problem shapes (fixed)
#define MDIM 8192
#define KDIM 4096
#define NDIM 4096

// ---------------- scratch (device globals; no allocation) ----------------
__device__ __nv_bfloat16 g_Xs[(size_t)MDIM * KDIM];   // 2:4-sparsified fp8-grid X values (exact in bf16)
__device__ __nv_bfloat16 g_Wq[(size_t)NDIM * KDIM];   // fp8-grid W values
__device__ float g_xsc[MDIM];
__device__ float g_wsc[NDIM];

// ---------------- fp8 round-trip: value on e4m3 grid, in quantized units ----------------
__device__ __forceinline__ float fp8_value(float v, float scale) {
    float q = v / scale;  // IEEE RN division, same as jnp t/scale
    __nv_fp8_storage_t s = __nv_cvt_float_to_fp8(q, __NV_SATFINITE, __NV_E4M3);
    __half_raw hr = __nv_cvt_fp8_to_halfraw(s, __NV_E4M3);
    return __half2float(*reinterpret_cast<__half*>(&hr));
}

// ---------------- quantization: one block per row, 256 thr x 16 elems ----------------
template <bool SPARSIFY>
__device__ __forceinline__ void quant_body(const float* __restrict__ in,
                                           __nv_bfloat16* __restrict__ outq,
                                           float* __restrict__ scales) {
    const int row = blockIdx.x;
    const float* src = in + (size_t)row * KDIM;
    const int t = threadIdx.x;

    float v[16];
#pragma unroll
    for (int i = 0; i < 4; i++) {
        float4 f = reinterpret_cast<const float4*>(src)[t * 4 + i];
        v[i * 4 + 0] = f.x; v[i * 4 + 1] = f.y;
        v[i * 4 + 2] = f.z; v[i * 4 + 3] = f.w;
    }

    float am = 0.0f;
#pragma unroll
    for (int i = 0; i < 16; i++) am = fmaxf(am, fabsf(v[i]));
#pragma unroll
    for (int o = 16; o > 0; o >>= 1) am = fmaxf(am, __shfl_xor_sync(0xffffffffu, am, o));

    __shared__ float warpmax[8];
    if ((t & 31) == 0) warpmax[t >> 5] = am;
    __syncthreads();
    float amax = warpmax[0];
#pragma unroll
    for (int w = 1; w < 8; w++) amax = fmaxf(amax, warpmax[w]);

    const float scale = fmaxf(amax, 1e-12f) / 448.0f;
    if (t == 0) scales[row] = scale;

    __align__(16) __nv_bfloat16 o[16];
#pragma unroll
    for (int g = 0; g < 4; g++) {
        float d[4];
#pragma unroll
        for (int j = 0; j < 4; j++) d[j] = fp8_value(v[g * 4 + j], scale);
        if (SPARSIFY) {
            float mg[4];
#pragma unroll
            for (int j = 0; j < 4; j++) mg[j] = fabsf(d[j]);
#pragma unroll
            for (int j = 0; j < 4; j++) {
                int rank = 0;
#pragma unroll
                for (int l = 0; l < 4; l++)
                    rank += (mg[l] > mg[j]) || (mg[l] == mg[j] && l < j);
                if (rank >= 2) d[j] = 0.0f;   // keep the 2 largest (stable tie-break)
            }
        }
#pragma unroll
        for (int j = 0; j < 4; j++) o[g * 4 + j] = __float2bfloat16(d[j]);
    }

    uint4* dst = reinterpret_cast<uint4*>(outq + (size_t)row * KDIM) + t * 2;
    dst[0] = *reinterpret_cast<const uint4*>(&o[0]);
    dst[1] = *reinterpret_cast<const uint4*>(&o[8]);
}

__global__ void __launch_bounds__(256) quant_x_run(const float* __restrict__ x) {
    quant_body<true>(x, g_Xs, g_xsc);
}
__global__ void __launch_bounds__(256) quant_w_run(const float* __restrict__ w) {
    quant_body<false>(w, g_Wq, g_wsc);
}

// ---------------- GEMM: out = Xs @ Wq^T with fused scales, FLOAT32 output ----------------
#define BM 128
#define BN 128
#define BK 64
#define STAGES 3
constexpr int TILE_ELEMS = BM * BK;                              // 8192 bf16
constexpr unsigned SMEM_BYTES = STAGES * 2 * TILE_ELEMS * 2;     // 96 KB

__device__ __forceinline__ int swz(int row, int kc) {
    // 128B rows, 16B chunks, XOR swizzle -> conflict-free ldmatrix & cp.async
    return row * BK + ((kc ^ (row & 7)) << 3);   // in bf16 elements
}

__device__ __forceinline__ void cp_async16(void* smem_ptr, const void* gmem_ptr) {
    uint32_t s = (uint32_t)__cvta_generic_to_shared(smem_ptr);
    asm volatile("cp.async.cg.shared.global [%0], [%1], 16;\n" :: "r"(s), "l"(gmem_ptr));
}

__global__ void __launch_bounds__(256) gemm_kernel(float* __restrict__ out) {
    extern __shared__ __align__(128) unsigned char smem_raw[];
    __nv_bfloat16* sA = reinterpret_cast<__nv_bfloat16*>(smem_raw);
    __nv_bfloat16* sB = sA + STAGES * TILE_ELEMS;

    const int bm = blockIdx.y * BM;
    const int bn = blockIdx.x * BN;
    const int tid = threadIdx.x;
    const int lane = tid & 31;
    const int gid = lane >> 2;
    const int tig = lane & 3;
    const int warp = tid >> 5;
    const int wm = (warp >> 1) * 32;   // 4 warps along M
    const int wn = (warp & 1) * 64;    // 2 warps along N

    const __nv_bfloat16* gA = g_Xs + (size_t)bm * KDIM;
    const __nv_bfloat16* gB = g_Wq + (size_t)bn * KDIM;

    auto load_tile = [&](int kt, int s) {
        const __nv_bfloat16* a = gA + kt * BK;
        const __nv_bfloat16* b = gB + kt * BK;
#pragma unroll
        for (int p = 0; p < 4; p++) {
            int chunk = p * 256 + tid;
            int row = chunk >> 3, kc = chunk & 7;
            cp_async16(sA + s * TILE_ELEMS + swz(row, kc), a + (size_t)row * KDIM + kc * 8);
        }
#pragma unroll
        for (int p = 0; p < 4; p++) {
            int chunk = p * 256 + tid;
            int row = chunk >> 3, kc = chunk & 7;
            cp_async16(sB + s * TILE_ELEMS + swz(row, kc), b + (size_t)row * KDIM + kc * 8);
        }
    };

    float acc[2][8][4];
#pragma unroll
    for (int i = 0; i < 2; i++)
#pragma unroll
        for (int j = 0; j < 8; j++)
#pragma unroll
            for (int c = 0; c < 4; c++) acc[i][j][c] = 0.0f;

    const int T = KDIM / BK;  // 64
    load_tile(0, 0); asm volatile("cp.async.commit_group;\n" ::: "memory");
    load_tile(1, 1); asm volatile("cp.async.commit_group;\n" ::: "memory");

    for (int t = 0; t < T; t++) {
        if (t + 2 < T) load_tile(t + 2, (t + 2) % STAGES);
        asm volatile("cp.async.commit_group;\n" ::: "memory");
        asm volatile("cp.async.wait_group 2;\n" ::: "memory");
        __syncthreads();

        const __nv_bfloat16* cA = sA + (t % STAGES) * TILE_ELEMS;
        const __nv_bfloat16* cB = sB + (t % STAGES) * TILE_ELEMS;

#pragma unroll
        for (int ks = 0; ks < 4; ks++) {
            uint32_t a[2][4];
#pragma unroll
            for (int mi = 0; mi < 2; mi++) {
                int row = wm + mi * 16 + (lane & 15);
                int kc = ks * 2 + (lane >> 4);
                uint32_t sa = (uint32_t)__cvta_generic_to_shared(cA + swz(row, kc));
                asm volatile("ldmatrix.sync.aligned.m8n8.x4.shared.b16 {%0,%1,%2,%3}, [%4];\n"
                             : "=r"(a[mi][0]), "=r"(a[mi][1]), "=r"(a[mi][2]), "=r"(a[mi][3])
                             : "r"(sa));
            }
            uint32_t b[8][2];
#pragma unroll
            for (int j = 0; j < 4; j++) {
                int row = wn + j * 16 + (lane & 15);
                int kc = ks * 2 + (lane >> 4);
                uint32_t sb = (uint32_t)__cvta_generic_to_shared(cB + swz(row, kc));
                uint32_t r0, r1, r2, r3;
                asm volatile("ldmatrix.sync.aligned.m8n8.x4.shared.b16 {%0,%1,%2,%3}, [%4];\n"
                             : "=r"(r0), "=r"(r1), "=r"(r2), "=r"(r3) : "r"(sb));
                b[2 * j][0] = r0; b[2 * j][1] = r2;
                b[2 * j + 1][0] = r1; b[2 * j + 1][1] = r3;
            }
#pragma unroll
            for (int mi = 0; mi < 2; mi++)
#pragma unroll
                for (int nj = 0; nj < 8; nj++) {
                    asm volatile(
                        "mma.sync.aligned.m16n8k16.row.col.f32.bf16.bf16.f32 "
                        "{%0,%1,%2,%3}, {%4,%5,%6,%7}, {%8,%9}, {%0,%1,%2,%3};\n"
                        : "+f"(acc[mi][nj][0]), "+f"(acc[mi][nj][1]),
                          "+f"(acc[mi][nj][2]), "+f"(acc[mi][nj][3])
                        : "r"(a[mi][0]), "r"(a[mi][1]), "r"(a[mi][2]), "r"(a[mi][3]),
                          "r"(b[nj][0]), "r"(b[nj][1]));
                }
        }
        __syncthreads();
    }

    // epilogue: out[m,n] = f32( bf16( acc * x_scale[m] * w_scale[n] ) ), stored as FLOAT32
#pragma unroll
    for (int mi = 0; mi < 2; mi++) {
#pragma unroll
        for (int h = 0; h < 2; h++) {
            int m = bm + wm + mi * 16 + h * 8 + gid;
            float xscale = g_xsc[m];
#pragma unroll
            for (int nj = 0; nj < 8; nj++) {
                int n = bn + wn + nj * 8 + tig * 2;
                float c0 = acc[mi][nj][h * 2 + 0] * xscale * g_wsc[n];
                float c1 = acc[mi][nj][h * 2 + 1] * xscale * g_wsc[n + 1];
                float2 pv;
                pv.x = __bfloat162float(__float2bfloat16(c0));  // match reference bf16 cast
                pv.y = __bfloat162float(__float2bfloat16(c1));
                *reinterpret_cast<float2*>(out + (size_t)m * NDIM + n) = pv;
            }
        }
    }
}

extern "C" void kernel_launch(void* const* d_in, const int* in_sizes, int n_in,
                              void* d_out, int out_size) {
    const float* in0 = (const float*)d_in[0];
    const float* in1 = (const float*)d_in[1];
    const float* x = in0;
    const float* w = in1;
    if (n_in >= 2 && in_sizes[0] == NDIM * KDIM && in_sizes[1] == MDIM * KDIM) {
        x = in1; w = in0;
    }
    float* out = (float*)d_out;   // __output__ is float32 (bf16-rounded values upcast)
    (void)out_size;

    cudaFuncSetAttribute(gemm_kernel, cudaFuncAttributeMaxDynamicSharedMemorySize, SMEM_BYTES);

    quant_x_run<<<MDIM, 256>>>(x);
    quant_w_run<<<NDIM, 256>>>(w);

    dim3 grid(NDIM / BN, MDIM / BM);   // (32, 64)
    gemm_kernel<<<grid, 256, SMEM_BYTES>>>(out);
}